// round 1
// baseline (speedup 1.0000x reference)
#include <cuda_runtime.h>
#include <math.h>

#define G_TOT 2048
#define N100 (64*100*100)
#define N200 (64*200*200)

// ---------------- scratch (static device globals; no allocations) ----------------
__device__ __align__(128) float4 g_p0[2][G_TOT];   // u, v, rx, ry  (rx<0 => culled)
__device__ __align__(128) float4 g_p1[2][G_TOT];   // A, B, C, op
__device__ __align__(128) float g_bev0[N100];
__device__ __align__(128) float g_embT[N100];
__device__ __align__(128) float g_xA[N100];
__device__ __align__(128) float g_xB[N100];
__device__ __align__(128) float g_xC[N100];
__device__ __align__(128) float g_bev1[N200];
__device__ __align__(128) float g_bev1r[N200];
__device__ __align__(128) float g_yu[N200];
__device__ __align__(128) float g_t0[N200];
__device__ __align__(128) float g_yA[N200];
__device__ __align__(128) float g_yB[N200];
__device__ float g_stats[128];                     // per-channel (mu, rstd)

// ---------------- gaussian preprocessing ----------------
__global__ void prep_k(const float* __restrict__ means, const float* __restrict__ cov,
                       const float* __restrict__ opac)
{
    int g = blockIdx.x * blockDim.x + threadIdx.x;
    if (g >= G_TOT) return;
    float mx = means[g*3+0], my = means[g*3+1], mz = means[g*3+2];
    bool pos = (mx >= -50.f) && (mx <= 50.f) && (my >= -50.f) && (my <= 50.f)
            && (mz >= -4.f)  && (mz <= 4.f);
    float c0 = cov[g*6+0], c1 = cov[g*6+1], c3 = cov[g*6+3];
    #pragma unroll
    for (int s = 0; s < 2; s++) {
        float H  = (s == 0) ? 100.f : 200.f;
        float sh = (s == 0) ? 1.f   : 2.f;
        float op = opac[g*2+s];
        bool mk = pos && (op > 0.05f);
        float u = -sh*my + 0.5f*H;
        float v = -sh*mx + 0.5f*H;
        float a  = sh*sh*c3 + 0.3f;
        float cc = sh*sh*c0 + 0.3f;
        float bb = sh*sh*c1;
        float det = fmaxf(a*cc - bb*bb, 1e-8f);
        float inv = 1.f/det;
        float A = cc*inv, Bc = -bb*inv, C = a*inv;
        float ct = logf(255.f*fmaxf(op, 1e-20f));
        float rx = sqrtf(fmaxf(2.f*ct*a , 0.f));
        float ry = sqrtf(fmaxf(2.f*ct*cc, 0.f));
        if (!mk) rx = -1.f;
        g_p0[s][g] = make_float4(u, v, rx, ry);
        g_p1[s][g] = make_float4(A, Bc, C, op);
    }
}

// ---------------- num_g ----------------
__global__ void numg_k(const float* __restrict__ means, const float* __restrict__ opac,
                       float* __restrict__ out, int out_size)
{
    __shared__ int red[256];
    int tid = threadIdx.x;
    int cnt = 0;
    for (int g = tid; g < G_TOT; g += 256) {
        float mx = means[g*3], my = means[g*3+1], mz = means[g*3+2];
        bool pos = (mx >= -50.f) && (mx <= 50.f) && (my >= -50.f) && (my <= 50.f)
                && (mz >= -4.f) && (mz <= 4.f);
        if (pos) {
            if (opac[g*2+0] > 0.05f) cnt++;
            if (opac[g*2+1] > 0.05f) cnt++;
        }
    }
    red[tid] = cnt; __syncthreads();
    for (int st = 128; st > 0; st >>= 1) {
        if (tid < st) red[tid] += red[tid+st];
        __syncthreads();
    }
    if (tid == 0 && out_size > 64*200*200) out[64*200*200] = (float)red[0];
}

// ---------------- tiled ordered splatting (16x16 tiles, 256 thr) ----------------
__global__ void render_k(int s, const float* __restrict__ feats,
                         float* __restrict__ out, int H)
{
    const int W = H;
    __shared__ int s_list[G_TOT];
    __shared__ int s_wcnt[8];
    int tid = threadIdx.x;
    int lane = tid & 31, wid = tid >> 5;
    int tx0 = blockIdx.x * 16, ty0 = blockIdx.y * 16;
    float xmin = (float)tx0, xmax = (float)min(tx0 + 15, W - 1);
    float ymin = (float)ty0, ymax = (float)min(ty0 + 15, H - 1);

    // phase 1: build index-ordered list of overlapping gaussians
    int num = 0;
    for (int base = 0; base < G_TOT; base += 256) {
        int g = base + tid;
        float4 q = g_p0[s][g];
        bool ok = (q.z >= 0.f) &&
                  (q.x + q.z >= xmin) && (q.x - q.z <= xmax) &&
                  (q.y + q.w >= ymin) && (q.y - q.w <= ymax);
        unsigned m = __ballot_sync(0xffffffffu, ok);
        if (lane == 0) s_wcnt[wid] = __popc(m);
        __syncthreads();
        int off = num + __popc(m & ((1u << lane) - 1u));
        int tot = 0;
        #pragma unroll
        for (int w2 = 0; w2 < 8; w2++) {
            int c = s_wcnt[w2];
            if (w2 < wid) off += c;
            tot += c;
        }
        if (ok) s_list[off] = g;
        num += tot;
        __syncthreads();
    }

    // phase 2: per-pixel front-to-back compositing in index order
    int px = tx0 + (tid & 15);
    int py = ty0 + (tid >> 4);
    float fx = (float)px, fy = (float)py;
    float T = 1.f;
    float acc[64];
    #pragma unroll
    for (int d = 0; d < 64; d++) acc[d] = 0.f;

    for (int i = 0; i < num; i++) {
        int g = s_list[i];
        float4 q = g_p0[s][g];
        float4 r = g_p1[s][g];
        float dx = q.x - fx, dy = q.y - fy;
        float power = -0.5f*(r.x*dx*dx + r.z*dy*dy) - r.y*dx*dy;
        float alpha = fminf(r.w * expf(power), 0.99f);
        if (alpha >= (1.f/255.f) && power <= 0.f) {
            float wg = alpha * T;
            T *= (1.f - alpha);
            const float4* f4 = (const float4*)(feats + (size_t)g * 64);
            #pragma unroll
            for (int j = 0; j < 16; j++) {
                float4 fv = __ldg(f4 + j);
                acc[4*j+0] += wg*fv.x;
                acc[4*j+1] += wg*fv.y;
                acc[4*j+2] += wg*fv.z;
                acc[4*j+3] += wg*fv.w;
            }
        }
    }
    if (px < W && py < H) {
        #pragma unroll
        for (int d = 0; d < 64; d++) out[d*H*W + py*W + px] = acc[d];
    }
}

// ---------------- bev_emb transpose: [p][d] -> [d][p] ----------------
__global__ void transpose_emb_k(const float* __restrict__ emb, float* __restrict__ out)
{
    int idx = blockIdx.x * 256 + threadIdx.x;
    if (idx >= 64*10000) return;
    int d = idx / 10000;
    int p = idx - d * 10000;
    out[idx] = emb[p*64 + d];
}

// ---------------- direct conv3x3, 64->64, optional add + relu ----------------
// block: 256 thr; tile 32x16 spatial x 16 output channels; thread: 8 co x 4 px
#define CTW 32
#define CTH 16
#define CICH 8
#define COG 16

__global__ void conv3x3_k(const float* __restrict__ in, const float* __restrict__ wgt,
                          const float* __restrict__ add, float* __restrict__ out,
                          int H, int W, int relu)
{
    __shared__ float s_in[CICH][CTH+2][CTW+3];   // stride 35: conflict-free reads
    __shared__ float s_w[COG][CICH][9];

    int tid  = threadIdx.x;
    int half = tid >> 7;          // 0/1 -> co offset 8*half (uniform within warp)
    int quad = tid & 127;
    int qx = quad & 7;            // 4-px strip: x = x0 + qx*4 + p
    int qy = quad >> 3;           // row within tile
    int x0 = blockIdx.x * CTW;
    int y0 = blockIdx.y * CTH;
    int co0 = blockIdx.z * COG;
    int HW = H * W;

    float acc[8][4];
    #pragma unroll
    for (int i = 0; i < 8; i++)
        #pragma unroll
        for (int j = 0; j < 4; j++) acc[i][j] = 0.f;

    for (int cb = 0; cb < 64; cb += CICH) {
        const int INEL = CICH * (CTH+2) * (CTW+2);   // 8*18*34
        for (int i = tid; i < INEL; i += 256) {
            int ci  = i / (18*34);
            int rem = i - ci * (18*34);
            int r = rem / 34;
            int c = rem - r * 34;
            int gy = y0 - 1 + r;
            int gx = x0 - 1 + c;
            float v = 0.f;
            if (gy >= 0 && gy < H && gx >= 0 && gx < W)
                v = in[(cb+ci)*HW + gy*W + gx];
            s_in[ci][r][c] = v;
        }
        const int WEL = COG * CICH * 9;              // 1152
        for (int i = tid; i < WEL; i += 256) {
            int co  = i / (CICH*9);
            int rem = i - co * (CICH*9);
            int ci = rem / 9;
            int k  = rem - ci * 9;
            s_w[co][ci][k] = wgt[(co0+co)*576 + (cb+ci)*9 + k];
        }
        __syncthreads();

        #pragma unroll 2
        for (int ci = 0; ci < CICH; ci++) {
            float iv[3][6];
            #pragma unroll
            for (int r = 0; r < 3; r++)
                #pragma unroll
                for (int c = 0; c < 6; c++)
                    iv[r][c] = s_in[ci][qy + r][qx*4 + c];
            #pragma unroll
            for (int co = 0; co < 8; co++) {
                float wv[9];
                #pragma unroll
                for (int k = 0; k < 9; k++) wv[k] = s_w[half*8 + co][ci][k];
                #pragma unroll
                for (int p = 0; p < 4; p++) {
                    float sum = acc[co][p];
                    #pragma unroll
                    for (int ky = 0; ky < 3; ky++)
                        #pragma unroll
                        for (int kx = 0; kx < 3; kx++)
                            sum = fmaf(wv[ky*3+kx], iv[ky][p+kx], sum);
                    acc[co][p] = sum;
                }
            }
        }
        __syncthreads();
    }

    int py  = y0 + qy;
    int pxb = x0 + qx * 4;
    if (py < H) {
        #pragma unroll
        for (int p = 0; p < 4; p++) {
            int x = pxb + p;
            if (x < W) {
                #pragma unroll
                for (int co = 0; co < 8; co++) {
                    int cch = co0 + half*8 + co;
                    float v = acc[co][p];
                    if (add)  v += add[cch*HW + py*W + x];
                    if (relu) v = fmaxf(v, 0.f);
                    out[cch*HW + py*W + x] = v;
                }
            }
        }
    }
}

// ---------------- bilinear 2x upsample (jax half-pixel + edge clamp) ----------------
__global__ void upsample_k(const float* __restrict__ in, float* __restrict__ out)
{
    int idx = blockIdx.x * 256 + threadIdx.x;
    if (idx >= 64*200*200) return;
    int x = idx % 200;
    int t = idx / 200;
    int y = t % 200;
    int c = t / 200;
    float sx = 0.5f*x - 0.25f;
    float sy = 0.5f*y - 0.25f;
    float fx = floorf(sx), fy = floorf(sy);
    float tx = sx - fx, ty = sy - fy;
    int x0 = max((int)fx, 0), x1 = min((int)fx + 1, 99);
    int y0 = max((int)fy, 0), y1 = min((int)fy + 1, 99);
    const float* p = in + c * 10000;
    float v00 = p[y0*100+x0], v01 = p[y0*100+x1];
    float v10 = p[y1*100+x0], v11 = p[y1*100+x1];
    out[idx] = (1.f-ty)*((1.f-tx)*v00 + tx*v01) + ty*((1.f-tx)*v10 + tx*v11);
}

// ---------------- instance norm ----------------
__global__ void in_reduce_k(const float* __restrict__ x)
{
    int c = blockIdx.x;
    const float* p = x + c * 40000;
    float s = 0.f, s2 = 0.f;
    for (int i = threadIdx.x; i < 40000; i += 256) { float v = p[i]; s += v; s2 += v*v; }
    __shared__ float rs[256], rq[256];
    rs[threadIdx.x] = s; rq[threadIdx.x] = s2;
    __syncthreads();
    for (int st = 128; st > 0; st >>= 1) {
        if (threadIdx.x < st) { rs[threadIdx.x] += rs[threadIdx.x+st]; rq[threadIdx.x] += rq[threadIdx.x+st]; }
        __syncthreads();
    }
    if (threadIdx.x == 0) {
        float mu  = rs[0] * (1.f/40000.f);
        float var = rq[0] * (1.f/40000.f) - mu*mu;
        g_stats[c*2]   = mu;
        g_stats[c*2+1] = 1.f/sqrtf(var + 1e-5f);
    }
}

__global__ void in_apply_k(const float* __restrict__ t, const float* __restrict__ add,
                           float* __restrict__ out)
{
    int idx = blockIdx.x * 256 + threadIdx.x;
    if (idx >= 64*40000) return;
    int c = idx / 40000;
    out[idx] = (t[idx] - g_stats[c*2]) * g_stats[c*2+1] + add[idx];
}

// ---------------- launch ----------------
extern "C" void kernel_launch(void* const* d_in, const int* in_sizes, int n_in,
                              void* d_out, int out_size)
{
    const float* features = (const float*)d_in[0];
    const float* means    = (const float*)d_in[1];
    const float* cov      = (const float*)d_in[2];
    const float* opac     = (const float*)d_in[3];
    const float* emb      = (const float*)d_in[4];
    const float* conv1w   = (const float*)d_in[5];
    const float* blkw     = (const float*)d_in[6];
    const float* upw      = (const float*)d_in[7];
    float* out = (float*)d_out;

    float *bev0,*embT,*xA,*xB,*xC,*bev1,*bev1r,*yu,*t0,*yA,*yB;
    cudaGetSymbolAddress((void**)&bev0,  g_bev0);
    cudaGetSymbolAddress((void**)&embT,  g_embT);
    cudaGetSymbolAddress((void**)&xA,    g_xA);
    cudaGetSymbolAddress((void**)&xB,    g_xB);
    cudaGetSymbolAddress((void**)&xC,    g_xC);
    cudaGetSymbolAddress((void**)&bev1,  g_bev1);
    cudaGetSymbolAddress((void**)&bev1r, g_bev1r);
    cudaGetSymbolAddress((void**)&yu,    g_yu);
    cudaGetSymbolAddress((void**)&t0,    g_t0);
    cudaGetSymbolAddress((void**)&yA,    g_yA);
    cudaGetSymbolAddress((void**)&yB,    g_yB);

    prep_k<<<8, 256>>>(means, cov, opac);
    numg_k<<<1, 256>>>(means, opac, out, out_size);
    render_k<<<dim3(7,7),   256>>>(0, features, bev0, 100);
    render_k<<<dim3(13,13), 256>>>(1, features, bev1, 200);
    transpose_emb_k<<<2500, 256>>>(emb, embT);

    dim3 cb(256);
    dim3 g100(4, 7, 4);    // ceil(100/32), ceil(100/16), 64/16
    dim3 g200(7, 13, 4);   // ceil(200/32), ceil(200/16), 64/16

    // stage 0 @100x100
    conv3x3_k<<<g100, cb>>>(bev0, conv1w + 0,        embT,    xA, 100, 100, 0);
    conv3x3_k<<<g100, cb>>>(xA,   blkw + 0*36864,    nullptr, xB, 100, 100, 1);
    conv3x3_k<<<g100, cb>>>(xB,   blkw + 1*36864,    xA,      xC, 100, 100, 1);
    conv3x3_k<<<g100, cb>>>(xC,   blkw + 2*36864,    nullptr, xA, 100, 100, 1);
    conv3x3_k<<<g100, cb>>>(xA,   blkw + 3*36864,    xC,      xB, 100, 100, 1);

    // stage 1 @200x200
    conv3x3_k<<<g200, cb>>>(bev1, conv1w + 36864,    nullptr, bev1r, 200, 200, 0);
    upsample_k<<<10000, 256>>>(xB, yu);
    conv3x3_k<<<g200, cb>>>(yu,   upw,               nullptr, t0,    200, 200, 0);
    in_reduce_k<<<64, 256>>>(t0);
    in_apply_k<<<10000, 256>>>(t0, bev1r, yA);
    conv3x3_k<<<g200, cb>>>(yA,   blkw + 4*36864,    nullptr, yB,  200, 200, 1);
    conv3x3_k<<<g200, cb>>>(yB,   blkw + 5*36864,    yA,      t0,  200, 200, 1);
    conv3x3_k<<<g200, cb>>>(t0,   blkw + 6*36864,    nullptr, yB,  200, 200, 1);
    conv3x3_k<<<g200, cb>>>(yB,   blkw + 7*36864,    t0,      out, 200, 200, 1);
}